// round 11
// baseline (speedup 1.0000x reference)
#include <cuda_runtime.h>
#include <cuda_bf16.h>
#include <cuda_fp16.h>
#include <cstdint>

#define NMODELS 16
#define OUT_DIM 8

// packed per-model blob: 84 B-tiles (512B each, {b0h,b1h,b0l,b1l} per lane) + 200 bias floats
// hi = fp16(w), lo = fp16(w - hi)  -> B represented exactly to ~2^-23
#define OFF_L1   0        /* 16 tiles: kt<2, nt<8 */
#define OFF_L2   8192     /* 32 tiles: kt<4, nt<8 */
#define OFF_L3   24576
#define OFF_L4   40960    /* 4 tiles:  kt<4, nt=0 */
#define OFF_BIAS 43008    /* floats: b1[64] b2[64] b3[64] b4[8] */
#define MODEL_STRIDE 43904
#define NTHREADS 128
#define TILE_M   128

static __device__ __align__(128) unsigned char g_wpack[NMODELS * MODEL_STRIDE];

// pack two fp32 -> f16x2 (low half = first arg)
__device__ __forceinline__ uint32_t cvt2f(float lo, float hi) {
    uint32_t r;
    asm("cvt.rn.f16x2.f32 %0, %1, %2;" : "=r"(r) : "f"(hi), "f"(lo));
    return r;
}
// fused relu + pack two fp32 -> f16x2
__device__ __forceinline__ uint32_t cvt2f_relu(float lo, float hi) {
    uint32_t r;
    asm("cvt.rn.relu.f16x2.f32 %0, %1, %2;" : "=r"(r) : "f"(hi), "f"(lo));
    return r;
}
// hi/lo split of a pair into fp16 hi + fp16 residual
__device__ __forceinline__ void split_pair_f16(float v0, float v1, uint32_t& h, uint32_t& l) {
    h = cvt2f(v0, v1);
    float h0 = __half2float(__ushort_as_half((unsigned short)(h & 0xffffu)));
    float h1 = __half2float(__ushort_as_half((unsigned short)(h >> 16)));
    l = cvt2f(v0 - h0, v1 - h1);
}
__device__ __forceinline__ void mma_f16(float* c, const uint32_t* a, uint32_t b0, uint32_t b1) {
    asm volatile("mma.sync.aligned.m16n8k16.row.col.f32.f16.f16.f32 "
                 "{%0,%1,%2,%3}, {%4,%5,%6,%7}, {%8,%9}, {%0,%1,%2,%3};"
                 : "+f"(c[0]), "+f"(c[1]), "+f"(c[2]), "+f"(c[3])
                 : "r"(a[0]), "r"(a[1]), "r"(a[2]), "r"(a[3]), "r"(b0), "r"(b1));
}

// ---------------- prepass: fp32 weights -> fragment-packed fp16 hi/lo blob ----------------
__global__ void prep_weights(const float* __restrict__ W1, const float* __restrict__ b1,
                             const float* __restrict__ W2, const float* __restrict__ b2,
                             const float* __restrict__ W3, const float* __restrict__ b3,
                             const float* __restrict__ W4, const float* __restrict__ b4) {
    int i0 = blockIdx.x * blockDim.x + threadIdx.x;
    int stride = gridDim.x * blockDim.x;

    for (int e = i0; e < NMODELS * 84 * 32; e += stride) {
        int lane = e & 31;
        int t = (e >> 5) % 84;
        int m = e / (84 * 32);
        const float* W; int K, N, off, kt, nt;
        if (t < 16)      { W = W1; K = 32; N = 64; int tt = t;      kt = tt >> 3; nt = tt & 7; off = OFF_L1 + tt * 512; }
        else if (t < 48) { W = W2; K = 64; N = 64; int tt = t - 16; kt = tt >> 3; nt = tt & 7; off = OFF_L2 + tt * 512; }
        else if (t < 80) { W = W3; K = 64; N = 64; int tt = t - 48; kt = tt >> 3; nt = tt & 7; off = OFF_L3 + tt * 512; }
        else             { W = W4; K = 64; N = 8;  int tt = t - 80; kt = tt;      nt = 0;      off = OFF_L4 + tt * 512; }
        int g = lane >> 2, tg = lane & 3;
        int n = nt * 8 + g;
        int k0 = kt * 16 + tg * 2;
        const float* Wm = W + (size_t)m * K * N;
        float w00 = Wm[(k0 + 0) * N + n], w01 = Wm[(k0 + 1) * N + n];
        float w10 = Wm[(k0 + 8) * N + n], w11 = Wm[(k0 + 9) * N + n];
        uint32_t b0h, b0l, b1h, b1l;
        split_pair_f16(w00, w01, b0h, b0l);
        split_pair_f16(w10, w11, b1h, b1l);
        *(uint4*)(g_wpack + (size_t)m * MODEL_STRIDE + off + lane * 16) =
            make_uint4(b0h, b1h, b0l, b1l);
    }
    for (int e = i0; e < NMODELS * 200; e += stride) {
        int m = e / 200, j = e % 200;
        float v = (j < 64) ? b1[m * 64 + j] : (j < 128) ? b2[m * 64 + j - 64]
                : (j < 192) ? b3[m * 64 + j - 128] : b4[m * 8 + j - 192];
        ((float*)(g_wpack + (size_t)m * MODEL_STRIDE + OFF_BIAS))[j] = v;
    }
}

// ---------------- main kernel ----------------
// C tile n-range j: c0,c1 = (row g, cols 2tg,2tg+1), c2,c3 = (row g+8).
// A frag ktile kt: a0=(g, k0..k0+1) a1=(g+8) a2=(g, k0+8) a3=(g+8, k0+8).
// C->A identity: a0=pack(C[2kt].c0,c1) a1=pack(C[2kt].c2,c3) a2=pack(C[2kt+1].c0,c1) a3=...
//
// Passes: C = bias + A*Bh + A*Bl  (B exact via fp16 hi/lo; A single fp16)
// L1 additionally: + Al*Bh (input x kept exact via split)
// Bias is folded into accumulator INIT (off the critical path); relu is fused
// into the f16x2 pack via cvt.rn.relu -> inter-layer chain is MMA -> CVT -> MMA.

template<int KT, int NT, bool SPLIT_A>
__device__ __forceinline__ void run_layer(float c[2][8][4],
                                          const uint32_t* Ah, const uint32_t* Al,
                                          const uint4* __restrict__ wg,
                                          const float* __restrict__ bias, int tg) {
    if (NT == 1) {
        float2 b = *(const float2*)(bias + tg * 2);
#pragma unroll
        for (int mt = 0; mt < 2; mt++) {
            c[mt][0][0] = b.x; c[mt][0][1] = b.y; c[mt][0][2] = b.x; c[mt][0][3] = b.y;
            c[mt][1][0] = 0.f; c[mt][1][1] = 0.f; c[mt][1][2] = 0.f; c[mt][1][3] = 0.f;
        }
        // L4: alternate kt halves into c[mt][0] / c[mt][1] -> 4 chains, add at end
#pragma unroll
        for (int kt = 0; kt < KT; kt++) {
            uint4 B = __ldg(wg + kt * NT * 32);
            int acc = kt & 1;
#pragma unroll
            for (int mt = 0; mt < 2; mt++) {
                const uint32_t* a = Ah + (mt * KT + kt) * 4;
                mma_f16(c[mt][acc], a, B.x, B.y);
                mma_f16(c[mt][acc], a, B.z, B.w);
            }
        }
#pragma unroll
        for (int mt = 0; mt < 2; mt++)
#pragma unroll
            for (int i = 0; i < 4; i++) c[mt][0][i] += c[mt][1][i];
    } else {
#pragma unroll
        for (int nt = 0; nt < NT; nt++) {
            float2 b = *(const float2*)(bias + nt * 8 + tg * 2);
#pragma unroll
            for (int mt = 0; mt < 2; mt++) {
                c[mt][nt][0] = b.x; c[mt][nt][1] = b.y;
                c[mt][nt][2] = b.x; c[mt][nt][3] = b.y;
            }
        }
#pragma unroll
        for (int ntp = 0; ntp < NT / 2; ntp++) {
            const int j0 = 2 * ntp, j1 = 2 * ntp + 1;
#pragma unroll
            for (int kt = 0; kt < KT; kt++) {
                uint4 B0 = __ldg(wg + (kt * NT + j0) * 32);
                uint4 B1 = __ldg(wg + (kt * NT + j1) * 32);
#pragma unroll
                for (int mt = 0; mt < 2; mt++) {
                    const uint32_t* a = Ah + (mt * KT + kt) * 4;
                    mma_f16(c[mt][j0], a, B0.x, B0.y);   // A * B0h
                    mma_f16(c[mt][j1], a, B1.x, B1.y);   // A * B1h
                }
#pragma unroll
                for (int mt = 0; mt < 2; mt++) {
                    const uint32_t* a = Ah + (mt * KT + kt) * 4;
                    mma_f16(c[mt][j0], a, B0.z, B0.w);   // A * B0l
                    mma_f16(c[mt][j1], a, B1.z, B1.w);   // A * B1l
                }
                if (SPLIT_A) {
#pragma unroll
                    for (int mt = 0; mt < 2; mt++) {
                        const uint32_t* al = Al + (mt * KT + kt) * 4;
                        mma_f16(c[mt][j0], al, B0.x, B0.y);  // Al * B0h
                        mma_f16(c[mt][j1], al, B1.x, B1.y);  // Al * B1h
                    }
                }
            }
        }
    }
}

// relu + pack to single fp16 A-fragments (bias already in accumulators)
__device__ __forceinline__ void epilogue(const float c[2][8][4], uint32_t ah[2][4][4]) {
#pragma unroll
    for (int kt = 0; kt < 4; kt++) {
        int j0 = 2 * kt, j1 = 2 * kt + 1;
#pragma unroll
        for (int mt = 0; mt < 2; mt++) {
            ah[mt][kt][0] = cvt2f_relu(c[mt][j0][0], c[mt][j0][1]);
            ah[mt][kt][1] = cvt2f_relu(c[mt][j0][2], c[mt][j0][3]);
            ah[mt][kt][2] = cvt2f_relu(c[mt][j1][0], c[mt][j1][1]);
            ah[mt][kt][3] = cvt2f_relu(c[mt][j1][2], c[mt][j1][3]);
        }
    }
}

__global__ void __launch_bounds__(NTHREADS, 2)
ensemble_kernel(const float* __restrict__ x, float* __restrict__ out, int rows) {
    const int tid = threadIdx.x, wid = tid >> 5, lane = tid & 31;
    const int g = lane >> 2, tg = lane & 3;
    const int rowbase = blockIdx.x * TILE_M + wid * 32;

    // ---- X fragments (layer-1 A), fp16 hi/lo split, straight from gmem ----
    uint32_t xh[2][2][4], xl[2][2][4];
#pragma unroll
    for (int mt = 0; mt < 2; mt++) {
        int r0 = rowbase + mt * 16 + g;
#pragma unroll
        for (int kt = 0; kt < 2; kt++) {
            int k0 = kt * 16 + tg * 2;
            float2 v0 = *(const float2*)(x + (size_t)r0 * 32 + k0);
            float2 v1 = *(const float2*)(x + (size_t)(r0 + 8) * 32 + k0);
            float2 v2 = *(const float2*)(x + (size_t)r0 * 32 + k0 + 8);
            float2 v3 = *(const float2*)(x + (size_t)(r0 + 8) * 32 + k0 + 8);
            split_pair_f16(v0.x, v0.y, xh[mt][kt][0], xl[mt][kt][0]);
            split_pair_f16(v1.x, v1.y, xh[mt][kt][1], xl[mt][kt][1]);
            split_pair_f16(v2.x, v2.y, xh[mt][kt][2], xl[mt][kt][2]);
            split_pair_f16(v3.x, v3.y, xh[mt][kt][3], xl[mt][kt][3]);
        }
    }

    float s[2][4], sq[2][4];
#pragma unroll
    for (int mt = 0; mt < 2; mt++)
#pragma unroll
        for (int i = 0; i < 4; i++) { s[mt][i] = 0.f; sq[mt][i] = 0.f; }

    uint32_t ah[2][4][4];
    float c[2][8][4];

    for (int m = 0; m < NMODELS; m++) {
        const unsigned char* base = g_wpack + (size_t)m * MODEL_STRIDE;
        const uint4* wlane = (const uint4*)(base) + lane;   // lane-offset base (uint4 units)
        const float* bias = (const float*)(base + OFF_BIAS);

        run_layer<2, 8, true >(c, &xh[0][0][0], &xl[0][0][0], wlane + OFF_L1 / 16, bias + 0,   tg);
        epilogue(c, ah);
        run_layer<4, 8, false>(c, &ah[0][0][0], nullptr,      wlane + OFF_L2 / 16, bias + 64,  tg);
        epilogue(c, ah);
        run_layer<4, 8, false>(c, &ah[0][0][0], nullptr,      wlane + OFF_L3 / 16, bias + 128, tg);
        epilogue(c, ah);
        run_layer<4, 1, false>(c, &ah[0][0][0], nullptr,      wlane + OFF_L4 / 16, bias + 192, tg);

#pragma unroll
        for (int mt = 0; mt < 2; mt++)
#pragma unroll
            for (int i = 0; i < 4; i++) {
                float p = c[mt][0][i];          // bias already included
                s[mt][i] += p; sq[mt][i] += p * p;
            }
    }

    // ---- mean / unbiased std over 16 models ----
    size_t std_off = (size_t)rows * OUT_DIM;
#pragma unroll
    for (int mt = 0; mt < 2; mt++) {
#pragma unroll
        for (int half = 0; half < 2; half++) {
            int row = rowbase + mt * 16 + half * 8 + g;
            float sa = s[mt][half * 2], sb2 = s[mt][half * 2 + 1];
            float qa = sq[mt][half * 2], qb = sq[mt][half * 2 + 1];
            float mua = sa * (1.f / 16.f), mub = sb2 * (1.f / 16.f);
            float va = fmaxf((qa - sa * mua) * (1.f / 15.f), 0.f);
            float vb = fmaxf((qb - sb2 * mub) * (1.f / 15.f), 0.f);
            *(float2*)(out + (size_t)row * 8 + tg * 2) = make_float2(mua, mub);
            *(float2*)(out + std_off + (size_t)row * 8 + tg * 2) =
                make_float2(sqrtf(va), sqrtf(vb));
        }
    }
}

extern "C" void kernel_launch(void* const* d_in, const int* in_sizes, int n_in,
                              void* d_out, int out_size) {
    const float* x  = (const float*)d_in[0];
    const float* W1 = (const float*)d_in[1];
    const float* b1 = (const float*)d_in[2];
    const float* W2 = (const float*)d_in[3];
    const float* b2 = (const float*)d_in[4];
    const float* W3 = (const float*)d_in[5];
    const float* b3 = (const float*)d_in[6];
    const float* W4 = (const float*)d_in[7];
    const float* b4 = (const float*)d_in[8];
    float* out = (float*)d_out;
    int rows = in_sizes[0] / 32;

    prep_weights<<<128, 256>>>(W1, b1, W2, b2, W3, b3, W4, b4);
    ensemble_kernel<<<rows / TILE_M, NTHREADS>>>(x, out, rows);
}

// round 12
// speedup vs baseline: 1.5306x; 1.5306x over previous
#include <cuda_runtime.h>
#include <cuda_bf16.h>
#include <cuda_fp16.h>
#include <cstdint>

#define NMODELS 16
#define OUT_DIM 8

// packed per-model blob: 84 B-tiles (512B each, {b0h,b1h,b0l,b1l} per lane) + 200 bias floats
// hi = fp16(w), lo = fp16(w - hi)
#define OFF_L1   0        /* 16 tiles: kt<2, nt<8 */
#define OFF_L2   8192     /* 32 tiles: kt<4, nt<8 */
#define OFF_L3   24576
#define OFF_L4   40960    /* 4 tiles:  kt<4, nt=0 */
#define OFF_BIAS 43008    /* floats: b1[64] b2[64] b3[64] b4[8] */
#define MODEL_STRIDE 43904
#define NTHREADS 128
#define TILE_M   128

static __device__ __align__(128) unsigned char g_wpack[NMODELS * MODEL_STRIDE];

// pack two fp32 -> f16x2 (low half = first arg)
__device__ __forceinline__ uint32_t cvt2f(float lo, float hi) {
    uint32_t r;
    asm("cvt.rn.f16x2.f32 %0, %1, %2;" : "=r"(r) : "f"(hi), "f"(lo));
    return r;
}
// fused relu + pack two fp32 -> f16x2
__device__ __forceinline__ uint32_t cvt2f_relu(float lo, float hi) {
    uint32_t r;
    asm("cvt.rn.relu.f16x2.f32 %0, %1, %2;" : "=r"(r) : "f"(hi), "f"(lo));
    return r;
}
// hi/lo split of a pair into fp16 hi + fp16 residual
__device__ __forceinline__ void split_pair_f16(float v0, float v1, uint32_t& h, uint32_t& l) {
    h = cvt2f(v0, v1);
    float h0 = __half2float(__ushort_as_half((unsigned short)(h & 0xffffu)));
    float h1 = __half2float(__ushort_as_half((unsigned short)(h >> 16)));
    l = cvt2f(v0 - h0, v1 - h1);
}
__device__ __forceinline__ void mma_f16(float* c, const uint32_t* a, uint32_t b0, uint32_t b1) {
    asm volatile("mma.sync.aligned.m16n8k16.row.col.f32.f16.f16.f32 "
                 "{%0,%1,%2,%3}, {%4,%5,%6,%7}, {%8,%9}, {%0,%1,%2,%3};"
                 : "+f"(c[0]), "+f"(c[1]), "+f"(c[2]), "+f"(c[3])
                 : "r"(a[0]), "r"(a[1]), "r"(a[2]), "r"(a[3]), "r"(b0), "r"(b1));
}

// ---------------- prepass: fp32 weights -> fragment-packed fp16 hi/lo blob ----------------
__global__ void prep_weights(const float* __restrict__ W1, const float* __restrict__ b1,
                             const float* __restrict__ W2, const float* __restrict__ b2,
                             const float* __restrict__ W3, const float* __restrict__ b3,
                             const float* __restrict__ W4, const float* __restrict__ b4) {
    int i0 = blockIdx.x * blockDim.x + threadIdx.x;
    int stride = gridDim.x * blockDim.x;

    for (int e = i0; e < NMODELS * 84 * 32; e += stride) {
        int lane = e & 31;
        int t = (e >> 5) % 84;
        int m = e / (84 * 32);
        const float* W; int K, N, off, kt, nt;
        if (t < 16)      { W = W1; K = 32; N = 64; int tt = t;      kt = tt >> 3; nt = tt & 7; off = OFF_L1 + tt * 512; }
        else if (t < 48) { W = W2; K = 64; N = 64; int tt = t - 16; kt = tt >> 3; nt = tt & 7; off = OFF_L2 + tt * 512; }
        else if (t < 80) { W = W3; K = 64; N = 64; int tt = t - 48; kt = tt >> 3; nt = tt & 7; off = OFF_L3 + tt * 512; }
        else             { W = W4; K = 64; N = 8;  int tt = t - 80; kt = tt;      nt = 0;      off = OFF_L4 + tt * 512; }
        int g = lane >> 2, tg = lane & 3;
        int n = nt * 8 + g;
        int k0 = kt * 16 + tg * 2;
        const float* Wm = W + (size_t)m * K * N;
        float w00 = Wm[(k0 + 0) * N + n], w01 = Wm[(k0 + 1) * N + n];
        float w10 = Wm[(k0 + 8) * N + n], w11 = Wm[(k0 + 9) * N + n];
        uint32_t b0h, b0l, b1h, b1l;
        split_pair_f16(w00, w01, b0h, b0l);
        split_pair_f16(w10, w11, b1h, b1l);
        *(uint4*)(g_wpack + (size_t)m * MODEL_STRIDE + off + lane * 16) =
            make_uint4(b0h, b1h, b0l, b1l);
    }
    for (int e = i0; e < NMODELS * 200; e += stride) {
        int m = e / 200, j = e % 200;
        float v = (j < 64) ? b1[m * 64 + j] : (j < 128) ? b2[m * 64 + j - 64]
                : (j < 192) ? b3[m * 64 + j - 128] : b4[m * 8 + j - 192];
        ((float*)(g_wpack + (size_t)m * MODEL_STRIDE + OFF_BIAS))[j] = v;
    }
}

// ---------------- main kernel ----------------
// C tile n-range j: c0,c1 = (row g, cols 2tg,2tg+1), c2,c3 = (row g+8).
// A frag ktile kt: a0=(g, k0..k0+1) a1=(g+8) a2=(g, k0+8) a3=(g+8, k0+8).
// C->A identity: a0=pack(C[2kt].c0,c1) a1=pack(C[2kt].c2,c3) a2=pack(C[2kt+1].c0,c1) a3=...
//
// PASSES=3 (L1): bias + A*Bh + A*Bl + Al*Bh   (input exact)
// PASSES=1 (L2,L3): bias + A*Bh               (weights single fp16)
// PASSES=2 (L4): bias + A*Bh + A*Bl           (output weights exact)

template<int KT, int NT, int PASSES>
__device__ __forceinline__ void run_layer(float c[2][8][4],
                                          const uint32_t* Ah, const uint32_t* Al,
                                          const uint4* __restrict__ wg,
                                          const float* __restrict__ bias, int tg) {
    if (NT == 1) {
        float2 b = *(const float2*)(bias + tg * 2);
#pragma unroll
        for (int mt = 0; mt < 2; mt++) {
            c[mt][0][0] = b.x; c[mt][0][1] = b.y; c[mt][0][2] = b.x; c[mt][0][3] = b.y;
            c[mt][1][0] = 0.f; c[mt][1][1] = 0.f; c[mt][1][2] = 0.f; c[mt][1][3] = 0.f;
        }
        // L4: alternate kt halves into c[mt][0] / c[mt][1] -> 4 chains, add at end
#pragma unroll
        for (int kt = 0; kt < KT; kt++) {
            uint4 B = __ldg(wg + kt * NT * 32);
            int acc = kt & 1;
#pragma unroll
            for (int mt = 0; mt < 2; mt++) {
                const uint32_t* a = Ah + (mt * KT + kt) * 4;
                mma_f16(c[mt][acc], a, B.x, B.y);
                mma_f16(c[mt][acc], a, B.z, B.w);
            }
        }
#pragma unroll
        for (int mt = 0; mt < 2; mt++)
#pragma unroll
            for (int i = 0; i < 4; i++) c[mt][0][i] += c[mt][1][i];
    } else {
#pragma unroll
        for (int nt = 0; nt < NT; nt++) {
            float2 b = *(const float2*)(bias + nt * 8 + tg * 2);
#pragma unroll
            for (int mt = 0; mt < 2; mt++) {
                c[mt][nt][0] = b.x; c[mt][nt][1] = b.y;
                c[mt][nt][2] = b.x; c[mt][nt][3] = b.y;
            }
        }
#pragma unroll
        for (int ntp = 0; ntp < NT / 2; ntp++) {
            const int j0 = 2 * ntp, j1 = 2 * ntp + 1;
#pragma unroll
            for (int kt = 0; kt < KT; kt++) {
                if (PASSES == 1) {
                    // hi-only: load just the first 8B of each lane's 16B slot
                    uint2 B0 = __ldg((const uint2*)(wg + (kt * NT + j0) * 32));
                    uint2 B1 = __ldg((const uint2*)(wg + (kt * NT + j1) * 32));
#pragma unroll
                    for (int mt = 0; mt < 2; mt++) {
                        const uint32_t* a = Ah + (mt * KT + kt) * 4;
                        mma_f16(c[mt][j0], a, B0.x, B0.y);
                        mma_f16(c[mt][j1], a, B1.x, B1.y);
                    }
                } else {
                    uint4 B0 = __ldg(wg + (kt * NT + j0) * 32);
                    uint4 B1 = __ldg(wg + (kt * NT + j1) * 32);
#pragma unroll
                    for (int mt = 0; mt < 2; mt++) {
                        const uint32_t* a = Ah + (mt * KT + kt) * 4;
                        mma_f16(c[mt][j0], a, B0.x, B0.y);   // A * Bh
                        mma_f16(c[mt][j1], a, B1.x, B1.y);
                    }
#pragma unroll
                    for (int mt = 0; mt < 2; mt++) {
                        const uint32_t* a = Ah + (mt * KT + kt) * 4;
                        mma_f16(c[mt][j0], a, B0.z, B0.w);   // A * Bl
                        mma_f16(c[mt][j1], a, B1.z, B1.w);
                    }
                    if (PASSES >= 3) {
#pragma unroll
                        for (int mt = 0; mt < 2; mt++) {
                            const uint32_t* al = Al + (mt * KT + kt) * 4;
                            mma_f16(c[mt][j0], al, B0.x, B0.y);  // Al * Bh
                            mma_f16(c[mt][j1], al, B1.x, B1.y);
                        }
                    }
                }
            }
        }
    }
}

// relu + pack to single fp16 A-fragments (bias already in accumulators)
__device__ __forceinline__ void epilogue(const float c[2][8][4], uint32_t ah[2][4][4]) {
#pragma unroll
    for (int kt = 0; kt < 4; kt++) {
        int j0 = 2 * kt, j1 = 2 * kt + 1;
#pragma unroll
        for (int mt = 0; mt < 2; mt++) {
            ah[mt][kt][0] = cvt2f_relu(c[mt][j0][0], c[mt][j0][1]);
            ah[mt][kt][1] = cvt2f_relu(c[mt][j0][2], c[mt][j0][3]);
            ah[mt][kt][2] = cvt2f_relu(c[mt][j1][0], c[mt][j1][1]);
            ah[mt][kt][3] = cvt2f_relu(c[mt][j1][2], c[mt][j1][3]);
        }
    }
}

__global__ void __launch_bounds__(NTHREADS, 2)
ensemble_kernel(const float* __restrict__ x, float* __restrict__ out, int rows) {
    const int tid = threadIdx.x, wid = tid >> 5, lane = tid & 31;
    const int g = lane >> 2, tg = lane & 3;
    const int rowbase = blockIdx.x * TILE_M + wid * 32;

    // ---- X fragments (layer-1 A), fp16 hi/lo split, straight from gmem ----
    uint32_t xh[2][2][4], xl[2][2][4];
#pragma unroll
    for (int mt = 0; mt < 2; mt++) {
        int r0 = rowbase + mt * 16 + g;
#pragma unroll
        for (int kt = 0; kt < 2; kt++) {
            int k0 = kt * 16 + tg * 2;
            float2 v0 = *(const float2*)(x + (size_t)r0 * 32 + k0);
            float2 v1 = *(const float2*)(x + (size_t)(r0 + 8) * 32 + k0);
            float2 v2 = *(const float2*)(x + (size_t)r0 * 32 + k0 + 8);
            float2 v3 = *(const float2*)(x + (size_t)(r0 + 8) * 32 + k0 + 8);
            split_pair_f16(v0.x, v0.y, xh[mt][kt][0], xl[mt][kt][0]);
            split_pair_f16(v1.x, v1.y, xh[mt][kt][1], xl[mt][kt][1]);
            split_pair_f16(v2.x, v2.y, xh[mt][kt][2], xl[mt][kt][2]);
            split_pair_f16(v3.x, v3.y, xh[mt][kt][3], xl[mt][kt][3]);
        }
    }

    float s[2][4], sq[2][4];
#pragma unroll
    for (int mt = 0; mt < 2; mt++)
#pragma unroll
        for (int i = 0; i < 4; i++) { s[mt][i] = 0.f; sq[mt][i] = 0.f; }

    uint32_t ah[2][4][4];
    float c[2][8][4];

    for (int m = 0; m < NMODELS; m++) {
        const unsigned char* base = g_wpack + (size_t)m * MODEL_STRIDE;
        const uint4* wlane = (const uint4*)(base) + lane;   // lane-offset base (uint4 units)
        const float* bias = (const float*)(base + OFF_BIAS);

        run_layer<2, 8, 3>(c, &xh[0][0][0], &xl[0][0][0], wlane + OFF_L1 / 16, bias + 0,   tg);
        epilogue(c, ah);
        run_layer<4, 8, 1>(c, &ah[0][0][0], nullptr,      wlane + OFF_L2 / 16, bias + 64,  tg);
        epilogue(c, ah);
        run_layer<4, 8, 1>(c, &ah[0][0][0], nullptr,      wlane + OFF_L3 / 16, bias + 128, tg);
        epilogue(c, ah);
        run_layer<4, 1, 2>(c, &ah[0][0][0], nullptr,      wlane + OFF_L4 / 16, bias + 192, tg);

#pragma unroll
        for (int mt = 0; mt < 2; mt++)
#pragma unroll
            for (int i = 0; i < 4; i++) {
                float p = c[mt][0][i];          // bias already included
                s[mt][i] += p; sq[mt][i] += p * p;
            }
    }

    // ---- mean / unbiased std over 16 models ----
    size_t std_off = (size_t)rows * OUT_DIM;
#pragma unroll
    for (int mt = 0; mt < 2; mt++) {
#pragma unroll
        for (int half = 0; half < 2; half++) {
            int row = rowbase + mt * 16 + half * 8 + g;
            float sa = s[mt][half * 2], sb2 = s[mt][half * 2 + 1];
            float qa = sq[mt][half * 2], qb = sq[mt][half * 2 + 1];
            float mua = sa * (1.f / 16.f), mub = sb2 * (1.f / 16.f);
            float va = fmaxf((qa - sa * mua) * (1.f / 15.f), 0.f);
            float vb = fmaxf((qb - sb2 * mub) * (1.f / 15.f), 0.f);
            *(float2*)(out + (size_t)row * 8 + tg * 2) = make_float2(mua, mub);
            *(float2*)(out + std_off + (size_t)row * 8 + tg * 2) =
                make_float2(sqrtf(va), sqrtf(vb));
        }
    }
}

extern "C" void kernel_launch(void* const* d_in, const int* in_sizes, int n_in,
                              void* d_out, int out_size) {
    const float* x  = (const float*)d_in[0];
    const float* W1 = (const float*)d_in[1];
    const float* b1 = (const float*)d_in[2];
    const float* W2 = (const float*)d_in[3];
    const float* b2 = (const float*)d_in[4];
    const float* W3 = (const float*)d_in[5];
    const float* b3 = (const float*)d_in[6];
    const float* W4 = (const float*)d_in[7];
    const float* b4 = (const float*)d_in[8];
    float* out = (float*)d_out;
    int rows = in_sizes[0] / 32;

    prep_weights<<<128, 256>>>(W1, b1, W2, b2, W3, b3, W4, b4);
    ensemble_kernel<<<rows / TILE_M, NTHREADS>>>(x, out, rows);
}

// round 14
// speedup vs baseline: 1.6560x; 1.0819x over previous
#include <cuda_runtime.h>
#include <cuda_bf16.h>
#include <cuda_fp16.h>
#include <cstdint>

#define NMODELS 16
#define OUT_DIM 8

// packed per-model blob: 84 B-tiles (512B each, {b0h,b1h,b0l,b1l} per lane) + 200 bias floats
// hi = fp16(w), lo = fp16(w - hi)
#define OFF_L1   0        /* 16 tiles: kt<2, nt<8 */
#define OFF_L2   8192     /* 32 tiles: kt<4, nt<8 */
#define OFF_L3   24576
#define OFF_L4   40960    /* 4 tiles:  kt<4, nt=0 */
#define OFF_BIAS 43008    /* floats: b1[64] b2[64] b3[64] b4[8] */
#define MODEL_STRIDE 43904
#define NTHREADS 128
#define TILE_M   128

static __device__ __align__(128) unsigned char g_wpack[NMODELS * MODEL_STRIDE];

// pack two fp32 -> f16x2 (low half = first arg)
__device__ __forceinline__ uint32_t cvt2f(float lo, float hi) {
    uint32_t r;
    asm("cvt.rn.f16x2.f32 %0, %1, %2;" : "=r"(r) : "f"(hi), "f"(lo));
    return r;
}
// fused relu + pack two fp32 -> f16x2
__device__ __forceinline__ uint32_t cvt2f_relu(float lo, float hi) {
    uint32_t r;
    asm("cvt.rn.relu.f16x2.f32 %0, %1, %2;" : "=r"(r) : "f"(hi), "f"(lo));
    return r;
}
// hi/lo split of a pair into fp16 hi + fp16 residual
__device__ __forceinline__ void split_pair_f16(float v0, float v1, uint32_t& h, uint32_t& l) {
    h = cvt2f(v0, v1);
    float h0 = __half2float(__ushort_as_half((unsigned short)(h & 0xffffu)));
    float h1 = __half2float(__ushort_as_half((unsigned short)(h >> 16)));
    l = cvt2f(v0 - h0, v1 - h1);
}
__device__ __forceinline__ void mma_f16(float* c, const uint32_t* a, uint32_t b0, uint32_t b1) {
    asm volatile("mma.sync.aligned.m16n8k16.row.col.f32.f16.f16.f32 "
                 "{%0,%1,%2,%3}, {%4,%5,%6,%7}, {%8,%9}, {%0,%1,%2,%3};"
                 : "+f"(c[0]), "+f"(c[1]), "+f"(c[2]), "+f"(c[3])
                 : "r"(a[0]), "r"(a[1]), "r"(a[2]), "r"(a[3]), "r"(b0), "r"(b1));
}

// ---------------- prepass: fp32 weights -> fragment-packed fp16 hi/lo blob ----------------
__global__ void prep_weights(const float* __restrict__ W1, const float* __restrict__ b1,
                             const float* __restrict__ W2, const float* __restrict__ b2,
                             const float* __restrict__ W3, const float* __restrict__ b3,
                             const float* __restrict__ W4, const float* __restrict__ b4) {
    int i0 = blockIdx.x * blockDim.x + threadIdx.x;
    int stride = gridDim.x * blockDim.x;

    for (int e = i0; e < NMODELS * 84 * 32; e += stride) {
        int lane = e & 31;
        int t = (e >> 5) % 84;
        int m = e / (84 * 32);
        const float* W; int K, N, off, kt, nt;
        if (t < 16)      { W = W1; K = 32; N = 64; int tt = t;      kt = tt >> 3; nt = tt & 7; off = OFF_L1 + tt * 512; }
        else if (t < 48) { W = W2; K = 64; N = 64; int tt = t - 16; kt = tt >> 3; nt = tt & 7; off = OFF_L2 + tt * 512; }
        else if (t < 80) { W = W3; K = 64; N = 64; int tt = t - 48; kt = tt >> 3; nt = tt & 7; off = OFF_L3 + tt * 512; }
        else             { W = W4; K = 64; N = 8;  int tt = t - 80; kt = tt;      nt = 0;      off = OFF_L4 + tt * 512; }
        int g = lane >> 2, tg = lane & 3;
        int n = nt * 8 + g;
        int k0 = kt * 16 + tg * 2;
        const float* Wm = W + (size_t)m * K * N;
        float w00 = Wm[(k0 + 0) * N + n], w01 = Wm[(k0 + 1) * N + n];
        float w10 = Wm[(k0 + 8) * N + n], w11 = Wm[(k0 + 9) * N + n];
        uint32_t b0h, b0l, b1h, b1l;
        split_pair_f16(w00, w01, b0h, b0l);
        split_pair_f16(w10, w11, b1h, b1l);
        *(uint4*)(g_wpack + (size_t)m * MODEL_STRIDE + off + lane * 16) =
            make_uint4(b0h, b1h, b0l, b1l);
    }
    for (int e = i0; e < NMODELS * 200; e += stride) {
        int m = e / 200, j = e % 200;
        float v = (j < 64) ? b1[m * 64 + j] : (j < 128) ? b2[m * 64 + j - 64]
                : (j < 192) ? b3[m * 64 + j - 128] : b4[m * 8 + j - 192];
        ((float*)(g_wpack + (size_t)m * MODEL_STRIDE + OFF_BIAS))[j] = v;
    }
}

// ---------------- main kernel ----------------
// C tile n-range j: c0,c1 = (row g, cols 2tg,2tg+1), c2,c3 = (row g+8).
// A frag ktile kt: a0=(g, k0..k0+1) a1=(g+8) a2=(g, k0+8) a3=(g+8, k0+8).
// C->A identity: a0=pack(C[2kt].c0,c1) a1=pack(C[2kt].c2,c3) a2=pack(C[2kt+1].c0,c1) a3=...
//
// PASSES=2 (L1): bias + A*Bh + A*Bl   (weights exact; input single fp16)
// PASSES=1 (L2,L3,L4): bias + A*Bh    (weights single fp16)

template<int KT, int NT, int PASSES>
__device__ __forceinline__ void run_layer(float c[2][8][4],
                                          const uint32_t* Ah,
                                          const uint4* __restrict__ wg,
                                          const float* __restrict__ bias, int tg) {
    if (NT == 1) {
        float2 b = *(const float2*)(bias + tg * 2);
#pragma unroll
        for (int mt = 0; mt < 2; mt++) {
            c[mt][0][0] = b.x; c[mt][0][1] = b.y; c[mt][0][2] = b.x; c[mt][0][3] = b.y;
            c[mt][1][0] = 0.f; c[mt][1][1] = 0.f; c[mt][1][2] = 0.f; c[mt][1][3] = 0.f;
        }
        // L4: alternate kt halves into c[mt][0] / c[mt][1] -> 4 chains, add at end
#pragma unroll
        for (int kt = 0; kt < KT; kt++) {
            int acc = kt & 1;
            if (PASSES == 1) {
                uint2 B = __ldg((const uint2*)(wg + kt * 32));
#pragma unroll
                for (int mt = 0; mt < 2; mt++)
                    mma_f16(c[mt][acc], Ah + (mt * KT + kt) * 4, B.x, B.y);
            } else {
                uint4 B = __ldg(wg + kt * 32);
#pragma unroll
                for (int mt = 0; mt < 2; mt++) {
                    const uint32_t* a = Ah + (mt * KT + kt) * 4;
                    mma_f16(c[mt][acc], a, B.x, B.y);
                    mma_f16(c[mt][acc], a, B.z, B.w);
                }
            }
        }
#pragma unroll
        for (int mt = 0; mt < 2; mt++)
#pragma unroll
            for (int i = 0; i < 4; i++) c[mt][0][i] += c[mt][1][i];
    } else {
#pragma unroll
        for (int nt = 0; nt < NT; nt++) {
            float2 b = *(const float2*)(bias + nt * 8 + tg * 2);
#pragma unroll
            for (int mt = 0; mt < 2; mt++) {
                c[mt][nt][0] = b.x; c[mt][nt][1] = b.y;
                c[mt][nt][2] = b.x; c[mt][nt][3] = b.y;
            }
        }
#pragma unroll
        for (int ntp = 0; ntp < NT / 2; ntp++) {
            const int j0 = 2 * ntp, j1 = 2 * ntp + 1;
#pragma unroll
            for (int kt = 0; kt < KT; kt++) {
                if (PASSES == 1) {
                    // hi-only: load just the first 8B of each lane's 16B slot
                    uint2 B0 = __ldg((const uint2*)(wg + (kt * NT + j0) * 32));
                    uint2 B1 = __ldg((const uint2*)(wg + (kt * NT + j1) * 32));
#pragma unroll
                    for (int mt = 0; mt < 2; mt++) {
                        const uint32_t* a = Ah + (mt * KT + kt) * 4;
                        mma_f16(c[mt][j0], a, B0.x, B0.y);
                        mma_f16(c[mt][j1], a, B1.x, B1.y);
                    }
                } else {
                    uint4 B0 = __ldg(wg + (kt * NT + j0) * 32);
                    uint4 B1 = __ldg(wg + (kt * NT + j1) * 32);
#pragma unroll
                    for (int mt = 0; mt < 2; mt++) {
                        const uint32_t* a = Ah + (mt * KT + kt) * 4;
                        mma_f16(c[mt][j0], a, B0.x, B0.y);   // A * Bh
                        mma_f16(c[mt][j1], a, B1.x, B1.y);
                    }
#pragma unroll
                    for (int mt = 0; mt < 2; mt++) {
                        const uint32_t* a = Ah + (mt * KT + kt) * 4;
                        mma_f16(c[mt][j0], a, B0.z, B0.w);   // A * Bl
                        mma_f16(c[mt][j1], a, B1.z, B1.w);
                    }
                }
            }
        }
    }
}

// relu + pack to single fp16 A-fragments (bias already in accumulators)
__device__ __forceinline__ void epilogue(const float c[2][8][4], uint32_t ah[2][4][4]) {
#pragma unroll
    for (int kt = 0; kt < 4; kt++) {
        int j0 = 2 * kt, j1 = 2 * kt + 1;
#pragma unroll
        for (int mt = 0; mt < 2; mt++) {
            ah[mt][kt][0] = cvt2f_relu(c[mt][j0][0], c[mt][j0][1]);
            ah[mt][kt][1] = cvt2f_relu(c[mt][j0][2], c[mt][j0][3]);
            ah[mt][kt][2] = cvt2f_relu(c[mt][j1][0], c[mt][j1][1]);
            ah[mt][kt][3] = cvt2f_relu(c[mt][j1][2], c[mt][j1][3]);
        }
    }
}

__global__ void __launch_bounds__(NTHREADS, 2)
ensemble_kernel(const float* __restrict__ x, float* __restrict__ out, int rows) {
    const int tid = threadIdx.x, wid = tid >> 5, lane = tid & 31;
    const int g = lane >> 2, tg = lane & 3;
    const int rowbase = blockIdx.x * TILE_M + wid * 32;

    // ---- X fragments (layer-1 A), single fp16, straight from gmem ----
    uint32_t xh[2][2][4];
#pragma unroll
    for (int mt = 0; mt < 2; mt++) {
        int r0 = rowbase + mt * 16 + g;
#pragma unroll
        for (int kt = 0; kt < 2; kt++) {
            int k0 = kt * 16 + tg * 2;
            float2 v0 = *(const float2*)(x + (size_t)r0 * 32 + k0);
            float2 v1 = *(const float2*)(x + (size_t)(r0 + 8) * 32 + k0);
            float2 v2 = *(const float2*)(x + (size_t)r0 * 32 + k0 + 8);
            float2 v3 = *(const float2*)(x + (size_t)(r0 + 8) * 32 + k0 + 8);
            xh[mt][kt][0] = cvt2f(v0.x, v0.y);
            xh[mt][kt][1] = cvt2f(v1.x, v1.y);
            xh[mt][kt][2] = cvt2f(v2.x, v2.y);
            xh[mt][kt][3] = cvt2f(v3.x, v3.y);
        }
    }

    float s[2][4], sq[2][4];
#pragma unroll
    for (int mt = 0; mt < 2; mt++)
#pragma unroll
        for (int i = 0; i < 4; i++) { s[mt][i] = 0.f; sq[mt][i] = 0.f; }

    uint32_t ah[2][4][4];
    float c[2][8][4];

    for (int m = 0; m < NMODELS; m++) {
        const unsigned char* base = g_wpack + (size_t)m * MODEL_STRIDE;
        const uint4* wlane = (const uint4*)(base) + lane;   // lane-offset base (uint4 units)
        const float* bias = (const float*)(base + OFF_BIAS);

        run_layer<2, 8, 2>(c, &xh[0][0][0], wlane + OFF_L1 / 16, bias + 0,   tg);
        epilogue(c, ah);
        run_layer<4, 8, 1>(c, &ah[0][0][0], wlane + OFF_L2 / 16, bias + 64,  tg);
        epilogue(c, ah);
        run_layer<4, 8, 1>(c, &ah[0][0][0], wlane + OFF_L3 / 16, bias + 128, tg);
        epilogue(c, ah);
        run_layer<4, 1, 1>(c, &ah[0][0][0], wlane + OFF_L4 / 16, bias + 192, tg);

#pragma unroll
        for (int mt = 0; mt < 2; mt++)
#pragma unroll
            for (int i = 0; i < 4; i++) {
                float p = c[mt][0][i];          // bias already included
                s[mt][i] += p; sq[mt][i] += p * p;
            }
    }

    // ---- mean / unbiased std over 16 models ----
    size_t std_off = (size_t)rows * OUT_DIM;
#pragma unroll
    for (int mt = 0; mt < 2; mt++) {
#pragma unroll
        for (int half = 0; half < 2; half++) {
            int row = rowbase + mt * 16 + half * 8 + g;
            float sa = s[mt][half * 2], sb2 = s[mt][half * 2 + 1];
            float qa = sq[mt][half * 2], qb = sq[mt][half * 2 + 1];
            float mua = sa * (1.f / 16.f), mub = sb2 * (1.f / 16.f);
            float va = fmaxf((qa - sa * mua) * (1.f / 15.f), 0.f);
            float vb = fmaxf((qb - sb2 * mub) * (1.f / 15.f), 0.f);
            *(float2*)(out + (size_t)row * 8 + tg * 2) = make_float2(mua, mub);
            *(float2*)(out + std_off + (size_t)row * 8 + tg * 2) =
                make_float2(sqrtf(va), sqrtf(vb));
        }
    }
}

extern "C" void kernel_launch(void* const* d_in, const int* in_sizes, int n_in,
                              void* d_out, int out_size) {
    const float* x  = (const float*)d_in[0];
    const float* W1 = (const float*)d_in[1];
    const float* b1 = (const float*)d_in[2];
    const float* W2 = (const float*)d_in[3];
    const float* b2 = (const float*)d_in[4];
    const float* W3 = (const float*)d_in[5];
    const float* b3 = (const float*)d_in[6];
    const float* W4 = (const float*)d_in[7];
    const float* b4 = (const float*)d_in[8];
    float* out = (float*)d_out;
    int rows = in_sizes[0] / 32;

    prep_weights<<<128, 256>>>(W1, b1, W2, b2, W3, b3, W4, b4);
    ensemble_kernel<<<rows / TILE_M, NTHREADS>>>(x, out, rows);
}